// round 2
// baseline (speedup 1.0000x reference)
#include <cuda_runtime.h>
#include <math.h>

#define Bn   128
#define Tn   400
#define Hn   512
#define H2n  1024
#define En   128
#define Vn   50000
#define EPSf 1e-12f

// ---- output layout (floats): concat of reference returns ----
#define O_FINAL 0
#define O_H     6400000
#define O_C     6465536
#define O_CT    6531072
#define O_ATTN  6662144
#define O_PGEN  6713344
#define O_COV   6713472

// ---- scratch (single device global, no allocations) ----
#define OFF_XIN    0        // [128,1152]
#define OFF_X      147456   // [128,128]
#define OFF_GATES  163840   // [128,2048]
#define OFF_STHAT  425984   // [128,1024]
#define OFF_DECFEA 557056   // [128,1024]
#define OFF_SCORES 688128   // [128,400]
#define OFF_HCT    739328   // [128,1536]
#define OFF_OUT1   935936   // [128,512]
#define SCRATCH_FLOATS 1001472

__device__ float g_scratch[SCRATCH_FLOATS];

__device__ __forceinline__ float warpReduceSum(float v) {
#pragma unroll
    for (int o = 16; o > 0; o >>= 1) v += __shfl_xor_sync(0xffffffffu, v, o);
    return v;
}
__device__ __forceinline__ float warpReduceMax(float v) {
#pragma unroll
    for (int o = 16; o > 0; o >>= 1) v = fmaxf(v, __shfl_xor_sync(0xffffffffu, v, o));
    return v;
}
__device__ __forceinline__ float sigmoidf_(float x) { return 1.f / (1.f + expf(-x)); }

// ---- K1: xin = concat(c_t_1, emb[y]) ----
__global__ void k_build_xin(const int* __restrict__ y, const float* __restrict__ ct1,
                            const float* __restrict__ emb, float* __restrict__ xin) {
    int b = blockIdx.x;
    int yy = y[b];
    for (int i = threadIdx.x; i < 1152; i += blockDim.x)
        xin[b * 1152 + i] = (i < 1024) ? ct1[b * 1024 + i] : emb[yy * 128 + (i - 1024)];
}

// ---- generic GEMM: C[M,N] (+)= A[M,K] @ B[N,K]^T + bias[N] ----
// BM=64, BN=64, BK=16, 256 threads, 4x4 micro-tile. M must be a multiple of 64.
__global__ __launch_bounds__(256) void k_gemm(const float* __restrict__ A,
                                              const float* __restrict__ Bm,
                                              const float* __restrict__ bias,
                                              float* __restrict__ C,
                                              int M, int N, int K, int accFlag) {
    __shared__ float As[16][64];
    __shared__ float Bs[16][64];
    int m0 = blockIdx.x * 64, n0 = blockIdx.y * 64;
    int tid = threadIdx.x;
    int lr = tid >> 2;            // 0..63
    int lc = (tid & 3) * 4;       // 0,4,8,12
    int ty = tid >> 4, tx = tid & 15;
    float acc[4][4] = {};

    for (int kt = 0; kt < K; kt += 16) {
        float4 av = *(const float4*)&A[(long long)(m0 + lr) * K + kt + lc];
        As[lc + 0][lr] = av.x; As[lc + 1][lr] = av.y;
        As[lc + 2][lr] = av.z; As[lc + 3][lr] = av.w;
        float4 bv = make_float4(0.f, 0.f, 0.f, 0.f);
        if (n0 + lr < N) bv = *(const float4*)&Bm[(long long)(n0 + lr) * K + kt + lc];
        Bs[lc + 0][lr] = bv.x; Bs[lc + 1][lr] = bv.y;
        Bs[lc + 2][lr] = bv.z; Bs[lc + 3][lr] = bv.w;
        __syncthreads();
#pragma unroll
        for (int kk = 0; kk < 16; kk++) {
            float4 a4 = *(const float4*)&As[kk][ty * 4];
            float4 b4 = *(const float4*)&Bs[kk][tx * 4];
            float ar[4] = {a4.x, a4.y, a4.z, a4.w};
            float br[4] = {b4.x, b4.y, b4.z, b4.w};
#pragma unroll
            for (int i = 0; i < 4; i++)
#pragma unroll
                for (int j = 0; j < 4; j++) acc[i][j] += ar[i] * br[j];
        }
        __syncthreads();
    }
#pragma unroll
    for (int i = 0; i < 4; i++) {
        int m = m0 + ty * 4 + i;
#pragma unroll
        for (int j = 0; j < 4; j++) {
            int n = n0 + tx * 4 + j;
            if (n < N) {
                float v = acc[i][j] + bias[n];
                if (accFlag) v += C[(long long)m * N + n];
                C[(long long)m * N + n] = v;
            }
        }
    }
}

// ---- K4: LSTM cell elementwise ----
__global__ void k_lstm(const float* __restrict__ gates, const float* __restrict__ c0,
                       float* __restrict__ out, float* __restrict__ sthat,
                       float* __restrict__ hct) {
    int b = blockIdx.x, j = threadIdx.x;   // 512 threads
    const float* g = gates + b * 2048;
    float ig = g[j], fg = g[512 + j], gg = g[1024 + j], og = g[1536 + j];
    float c = sigmoidf_(fg) * c0[b * 512 + j] + sigmoidf_(ig) * tanhf(gg);
    float h = sigmoidf_(og) * tanhf(c);
    out[O_H + b * 512 + j] = h;
    out[O_C + b * 512 + j] = c;
    sthat[b * 1024 + j] = h;
    sthat[b * 1024 + 512 + j] = c;
    hct[b * 1536 + j] = h;
}

// ---- K6: attention scores ----
__global__ __launch_bounds__(256) void k_attn_scores(const float* __restrict__ encf,
                                                     const float* __restrict__ decfea,
                                                     const float* __restrict__ cov,
                                                     const float* __restrict__ Wc,
                                                     const float* __restrict__ vw,
                                                     float* __restrict__ scores) {
    __shared__ float df[1024], wc[1024], vv[1024];
    __shared__ float red[8];
    int b = blockIdx.x;
    for (int i = threadIdx.x; i < 1024; i += 256) {
        df[i] = decfea[b * 1024 + i];
        wc[i] = Wc[i];
        vv[i] = vw[i];
    }
    __syncthreads();
    int t0 = blockIdx.y * 50;
    for (int tt = 0; tt < 50; tt++) {
        int t = t0 + tt;
        float cv = cov[b * 400 + t];
        const float* ef = encf + (long long)(b * 400 + t) * 1024;
        float local = 0.f;
#pragma unroll
        for (int i = 0; i < 4; i++) {
            int n = threadIdx.x + i * 256;
            float e = tanhf(ef[n] + df[n] + cv * wc[n]);
            local += e * vv[n];
        }
        local = warpReduceSum(local);
        if ((threadIdx.x & 31) == 0) red[threadIdx.x >> 5] = local;
        __syncthreads();
        if (threadIdx.x == 0) {
            float v = 0.f;
#pragma unroll
            for (int w = 0; w < 8; w++) v += red[w];
            scores[b * 400 + t] = v;
        }
        __syncthreads();
    }
}

// ---- K7: softmax over T, masking, renorm, coverage update ----
__global__ __launch_bounds__(128) void k_attn_softmax(const float* __restrict__ scores,
                                                      const float* __restrict__ mask,
                                                      const float* __restrict__ cov,
                                                      float* __restrict__ out) {
    __shared__ float sc[400];
    __shared__ float red[4];
    int b = blockIdx.x, tid = threadIdx.x;
    float mx = -1e30f;
    for (int t = tid; t < 400; t += 128) {
        float v = scores[b * 400 + t];
        sc[t] = v;
        mx = fmaxf(mx, v);
    }
    mx = warpReduceMax(mx);
    if ((tid & 31) == 0) red[tid >> 5] = mx;
    __syncthreads();
    mx = fmaxf(fmaxf(red[0], red[1]), fmaxf(red[2], red[3]));
    __syncthreads();

    float s = 0.f;
    for (int t = tid; t < 400; t += 128) {
        float e = expf(sc[t] - mx);
        sc[t] = e;
        s += e;
    }
    s = warpReduceSum(s);
    if ((tid & 31) == 0) red[tid >> 5] = s;
    __syncthreads();
    float denom = red[0] + red[1] + red[2] + red[3];
    __syncthreads();

    float s2 = 0.f;
    for (int t = tid; t < 400; t += 128) {
        float m = sc[t] / denom * mask[b * 400 + t];
        sc[t] = m;
        s2 += m;
    }
    s2 = warpReduceSum(s2);
    if ((tid & 31) == 0) red[tid >> 5] = s2;
    __syncthreads();
    float denom2 = red[0] + red[1] + red[2] + red[3] + EPSf;

    for (int t = tid; t < 400; t += 128) {
        float a = sc[t] / denom2;
        out[O_ATTN + b * 400 + t] = a;
        out[O_COV + b * 400 + t] = cov[b * 400 + t] + a;
    }
}

// ---- K8: context vector c_t = attn @ encoder_outputs ----
__global__ __launch_bounds__(256) void k_context(const float* __restrict__ encout,
                                                 const float* __restrict__ outbuf,
                                                 float* __restrict__ out,
                                                 float* __restrict__ hct) {
    __shared__ float at[400];
    int b = blockIdx.x;
    for (int i = threadIdx.x; i < 400; i += 256) at[i] = outbuf[O_ATTN + b * 400 + i];
    __syncthreads();
    int n = blockIdx.y * 256 + threadIdx.x;
    const float* ep = encout + (long long)b * 400 * 1024 + n;
    float a0 = 0.f, a1 = 0.f, a2 = 0.f, a3 = 0.f;
    for (int t = 0; t < 400; t += 4) {
        a0 += at[t + 0] * ep[(t + 0) * 1024];
        a1 += at[t + 1] * ep[(t + 1) * 1024];
        a2 += at[t + 2] * ep[(t + 2) * 1024];
        a3 += at[t + 3] * ep[(t + 3) * 1024];
    }
    float acc = (a0 + a1) + (a2 + a3);
    out[O_CT + b * 1024 + n] = acc;
    hct[b * 1536 + 512 + n] = acc;
}

// ---- K9: pointer-generator gate ----
__global__ __launch_bounds__(256) void k_pgen(const float* __restrict__ outbuf,
                                              const float* __restrict__ sthat,
                                              const float* __restrict__ x,
                                              const float* __restrict__ Wpg,
                                              const float* __restrict__ bpg,
                                              float* __restrict__ out) {
    __shared__ float red[8];
    int b = blockIdx.x, tid = threadIdx.x;
    float local = 0.f;
    for (int i = tid; i < 2176; i += 256) {
        float v;
        if (i < 1024)       v = outbuf[O_CT + b * 1024 + i];
        else if (i < 2048)  v = sthat[b * 1024 + (i - 1024)];
        else                v = x[b * 128 + (i - 2048)];
        local += Wpg[i] * v;
    }
    local = warpReduceSum(local);
    if ((tid & 31) == 0) red[tid >> 5] = local;
    __syncthreads();
    if (tid == 0) {
        float s = 0.f;
#pragma unroll
        for (int w = 0; w < 8; w++) s += red[w];
        out[O_PGEN + b] = sigmoidf_(s + bpg[0]);
    }
}

// ---- K12: softmax over V in place, scaled by p_gen ----
__global__ __launch_bounds__(256) void k_vocab_softmax(float* __restrict__ out) {
    __shared__ float red[8];
    int b = blockIdx.x, tid = threadIdx.x;
    float* row = out + (long long)b * Vn;

    float mx = -1e30f;
    for (int i = tid; i < Vn; i += 256) mx = fmaxf(mx, row[i]);
    mx = warpReduceMax(mx);
    if ((tid & 31) == 0) red[tid >> 5] = mx;
    __syncthreads();
    float m2 = red[0];
#pragma unroll
    for (int w = 1; w < 8; w++) m2 = fmaxf(m2, red[w]);
    __syncthreads();

    float s = 0.f;
    for (int i = tid; i < Vn; i += 256) s += expf(row[i] - m2);
    s = warpReduceSum(s);
    if ((tid & 31) == 0) red[tid >> 5] = s;
    __syncthreads();
    float tot = 0.f;
#pragma unroll
    for (int w = 0; w < 8; w++) tot += red[w];

    float scale = out[O_PGEN + b] / tot;
    for (int i = tid; i < Vn; i += 256) row[i] = expf(row[i] - m2) * scale;
}

// ---- K13: pointer scatter-add ----
__global__ void k_scatter(const int* __restrict__ ebev, const float* __restrict__ outbuf,
                          float* __restrict__ out) {
    int idx = blockIdx.x * blockDim.x + threadIdx.x;
    if (idx >= Bn * Tn) return;
    int b = idx / Tn;
    float add = (1.f - outbuf[O_PGEN + b]) * outbuf[O_ATTN + idx];
    atomicAdd(&out[(long long)b * Vn + ebev[idx]], add);
}

extern "C" void kernel_launch(void* const* d_in, const int* in_sizes, int n_in,
                              void* d_out, int out_size) {
    const int*   y      = (const int*)d_in[0];
    const float* h0     = (const float*)d_in[1];
    const float* c0     = (const float*)d_in[2];
    const float* ct1    = (const float*)d_in[3];
    const float* encout = (const float*)d_in[4];
    const float* encf   = (const float*)d_in[5];
    const float* mask   = (const float*)d_in[6];
    const int*   ebev   = (const int*)d_in[7];
    const float* cov    = (const float*)d_in[8];
    const float* emb    = (const float*)d_in[9];
    const float* Wc     = (const float*)d_in[10];
    const float* Wdp    = (const float*)d_in[11];
    const float* bdp    = (const float*)d_in[12];
    const float* vw     = (const float*)d_in[13];
    const float* Wxc    = (const float*)d_in[14];
    const float* bxc    = (const float*)d_in[15];
    const float* Wih    = (const float*)d_in[16];
    const float* Whh    = (const float*)d_in[17];
    const float* bih    = (const float*)d_in[18];
    const float* bhh    = (const float*)d_in[19];
    const float* Wpg    = (const float*)d_in[20];
    const float* bpg    = (const float*)d_in[21];
    const float* Wo1    = (const float*)d_in[22];
    const float* bo1    = (const float*)d_in[23];
    const float* Wo2    = (const float*)d_in[24];
    const float* bo2    = (const float*)d_in[25];
    float* out = (float*)d_out;

    float* scr = nullptr;
    cudaGetSymbolAddress((void**)&scr, g_scratch);
    float* xin    = scr + OFF_XIN;
    float* x      = scr + OFF_X;
    float* gates  = scr + OFF_GATES;
    float* sthat  = scr + OFF_STHAT;
    float* decfea = scr + OFF_DECFEA;
    float* scores = scr + OFF_SCORES;
    float* hct    = scr + OFF_HCT;
    float* out1   = scr + OFF_OUT1;

    // x = concat(c_t_1, emb[y]) @ W_xc^T + b_xc
    k_build_xin<<<128, 256>>>(y, ct1, emb, xin);
    k_gemm<<<dim3(2, 2), 256>>>(xin, Wxc, bxc, x, 128, 128, 1152, 0);

    // gates = x @ W_ih^T + b_ih + h0 @ W_hh^T + b_hh
    k_gemm<<<dim3(2, 32), 256>>>(x,  Wih, bih, gates, 128, 2048, 128, 0);
    k_gemm<<<dim3(2, 32), 256>>>(h0, Whh, bhh, gates, 128, 2048, 512, 1);
    k_lstm<<<128, 512>>>(gates, c0, out, sthat, hct);

    // attention
    k_gemm<<<dim3(2, 16), 256>>>(sthat, Wdp, bdp, decfea, 128, 1024, 1024, 0);
    k_attn_scores<<<dim3(128, 8), 256>>>(encf, decfea, cov, Wc, vw, scores);
    k_attn_softmax<<<128, 128>>>(scores, mask, cov, out);
    k_context<<<dim3(128, 4), 256>>>(encout, out, out, hct);

    // p_gen
    k_pgen<<<128, 256>>>(out, sthat, x, Wpg, bpg, out);

    // vocab distribution (logits written directly into final_dist region)
    k_gemm<<<dim3(2, 8), 256>>>(hct, Wo1, bo1, out1, 128, 512, 1536, 0);
    k_gemm<<<dim3(2, 782), 256>>>(out1, Wo2, bo2, out, 128, 50000, 512, 0);
    k_vocab_softmax<<<128, 256>>>(out);

    // pointer mixing
    k_scatter<<<200, 256>>>(ebev, out, out);
}

// round 7
// speedup vs baseline: 1.9034x; 1.9034x over previous
#include <cuda_runtime.h>
#include <math.h>
#include <stdint.h>

#define Bn   128
#define Tn   400
#define Vn   50000
#define EPSf 1e-12f

// ---- output layout (floats): concat of reference returns ----
#define O_FINAL 0
#define O_H     6400000
#define O_C     6465536
#define O_CT    6531072
#define O_ATTN  6662144
#define O_PGEN  6713344
#define O_COV   6713472

// ---- scratch ----
#define OFF_XIN    0        // [128,1152]
#define OFF_X      147456   // [128,128]
#define OFF_GATES  163840   // [128,2048]
#define OFF_STHAT  425984   // [128,1024]
#define OFF_DECFEA 557056   // [128,1024]
#define OFF_SCORES 688128   // [128,400]
#define OFF_HCT    739328   // [128,1536]
#define OFF_OUT1   935936   // [128,512]
#define SCRATCH_FLOATS 1001472

__device__ float g_scratch[SCRATCH_FLOATS];

__device__ __forceinline__ float warpReduceSum(float v) {
#pragma unroll
    for (int o = 16; o > 0; o >>= 1) v += __shfl_xor_sync(0xffffffffu, v, o);
    return v;
}
__device__ __forceinline__ float warpReduceMax(float v) {
#pragma unroll
    for (int o = 16; o > 0; o >>= 1) v = fmaxf(v, __shfl_xor_sync(0xffffffffu, v, o));
    return v;
}
__device__ __forceinline__ float sigmoidf_(float x) { return 1.f / (1.f + expf(-x)); }

__device__ __forceinline__ uint32_t f2tf32(float f) {
    uint32_t u;
    asm("cvt.rna.tf32.f32 %0, %1;" : "=r"(u) : "f"(f));
    return u;
}

__device__ __forceinline__ void mma_tf32(float* c, const uint32_t* a, const uint32_t* b) {
    asm("mma.sync.aligned.m16n8k8.row.col.f32.tf32.tf32.f32 "
        "{%0,%1,%2,%3}, {%4,%5,%6,%7}, {%8,%9}, {%0,%1,%2,%3};"
        : "+f"(c[0]), "+f"(c[1]), "+f"(c[2]), "+f"(c[3])
        : "r"(a[0]), "r"(a[1]), "r"(a[2]), "r"(a[3]), "r"(b[0]), "r"(b[1]));
}

// ================= tf32 tensor-core GEMM =================
// C[128, N] = A[128, K](lda) @ B[N, K]^T + bias1 + bias2 (+ C if acc)
// M = 128 always (1 block in M). grid.x = N tiles of (WN*32).
// 2 warps along M (64 rows each), WN warps along N (32 cols each).
// K must be a multiple of 32.
template<int WN>
__global__ void __launch_bounds__(WN * 64) k_mma(
        const float* __restrict__ A, const float* __restrict__ B,
        const float* __restrict__ bias1, const float* __restrict__ bias2,
        float* __restrict__ C, int N, int K, int lda, int ldc, int accFlag) {
    constexpr int NTHR = WN * 64;
    constexpr int TN   = WN * 32;
    constexpr int AF4  = 1024 / NTHR;       // A float4s per thread per chunk
    constexpr int BF4  = (TN * 8) / NTHR;   // B float4s per thread per chunk

    extern __shared__ uint32_t sm[];
    uint32_t* As = sm;                      // [2][128][36]
    uint32_t* Bs = sm + 2 * 128 * 36;       // [2][TN][36]

    const int tid  = threadIdx.x;
    const int wid  = tid >> 5, lane = tid & 31;
    const int g    = lane >> 2, t = lane & 3;
    const int n0   = blockIdx.x * TN;
    const int mw   = (wid / WN) * 64;
    const int nw   = (wid % WN) * 32;

    float acc[4][4][4] = {};
    float4 apf[AF4], bpf[BF4];

    const int nchunks = K >> 5;

#define GLOAD(KC)                                                              \
    {                                                                          \
        const float* Ap = A + (KC) * 32;                                       \
        _Pragma("unroll")                                                      \
        for (int i = 0; i < AF4; i++) {                                        \
            int e = tid + i * NTHR;                                            \
            int r = e >> 3, c4 = (e & 7) * 4;                                  \
            apf[i] = *(const float4*)(Ap + (long long)r * lda + c4);           \
        }                                                                      \
        const float* Bp = B + (KC) * 32;                                       \
        _Pragma("unroll")                                                      \
        for (int i = 0; i < BF4; i++) {                                        \
            int e = tid + i * NTHR;                                            \
            int r = e >> 3, c4 = (e & 7) * 4;                                  \
            int rg = n0 + r;                                                   \
            bpf[i] = (rg < N) ? *(const float4*)(Bp + (long long)rg * K + c4)  \
                              : make_float4(0.f, 0.f, 0.f, 0.f);               \
        }                                                                      \
    }

#define SSTORE(BUF)                                                            \
    {                                                                          \
        uint32_t* Asb = As + (BUF) * (128 * 36);                               \
        _Pragma("unroll")                                                      \
        for (int i = 0; i < AF4; i++) {                                        \
            int e = tid + i * NTHR;                                            \
            int r = e >> 3, c4 = (e & 7) * 4;                                  \
            uint4 u = make_uint4(f2tf32(apf[i].x), f2tf32(apf[i].y),           \
                                 f2tf32(apf[i].z), f2tf32(apf[i].w));          \
            *(uint4*)(Asb + r * 36 + c4) = u;                                  \
        }                                                                      \
        uint32_t* Bsb = Bs + (BUF) * (TN * 36);                                \
        _Pragma("unroll")                                                      \
        for (int i = 0; i < BF4; i++) {                                        \
            int e = tid + i * NTHR;                                            \
            int r = e >> 3, c4 = (e & 7) * 4;                                  \
            uint4 u = make_uint4(f2tf32(bpf[i].x), f2tf32(bpf[i].y),           \
                                 f2tf32(bpf[i].z), f2tf32(bpf[i].w));          \
            *(uint4*)(Bsb + r * 36 + c4) = u;                                  \
        }                                                                      \
    }

    GLOAD(0);
    SSTORE(0);
    __syncthreads();

    int buf = 0;
    for (int kc = 0; kc < nchunks; kc++) {
        bool more = (kc + 1 < nchunks);
        if (more) GLOAD(kc + 1);

        const uint32_t* Asb = As + buf * (128 * 36);
        const uint32_t* Bsb = Bs + buf * (TN * 36);
#pragma unroll
        for (int kk = 0; kk < 32; kk += 8) {
            uint32_t af[4][4], bf[4][2];
#pragma unroll
            for (int mt = 0; mt < 4; mt++) {
                const uint32_t* p = Asb + (mw + mt * 16 + g) * 36 + kk + t;
                af[mt][0] = p[0];
                af[mt][2] = p[4];
                af[mt][1] = p[8 * 36];
                af[mt][3] = p[8 * 36 + 4];
            }
#pragma unroll
            for (int nt = 0; nt < 4; nt++) {
                const uint32_t* p = Bsb + (nw + nt * 8 + g) * 36 + kk + t;
                bf[nt][0] = p[0];
                bf[nt][1] = p[4];
            }
#pragma unroll
            for (int mt = 0; mt < 4; mt++)
#pragma unroll
                for (int nt = 0; nt < 4; nt++)
                    mma_tf32(acc[mt][nt], af[mt], bf[nt]);
        }

        if (more) {
            SSTORE(buf ^ 1);
            __syncthreads();
        }
        buf ^= 1;
    }

    // epilogue
#pragma unroll
    for (int mt = 0; mt < 4; mt++) {
        int r = mw + mt * 16 + g;
#pragma unroll
        for (int nt = 0; nt < 4; nt++) {
            int c = n0 + nw + nt * 8 + 2 * t;
            if (c + 1 < N) {
                float b0 = (bias1 ? bias1[c] : 0.f) + (bias2 ? bias2[c] : 0.f);
                float b1 = (bias1 ? bias1[c + 1] : 0.f) + (bias2 ? bias2[c + 1] : 0.f);
                long long i0 = (long long)r * ldc + c;
                long long i1 = (long long)(r + 8) * ldc + c;
                float2 v0 = make_float2(acc[mt][nt][0] + b0, acc[mt][nt][1] + b1);
                float2 v1 = make_float2(acc[mt][nt][2] + b0, acc[mt][nt][3] + b1);
                if (accFlag) {
                    float2 o0 = *(float2*)&C[i0], o1 = *(float2*)&C[i1];
                    v0.x += o0.x; v0.y += o0.y; v1.x += o1.x; v1.y += o1.y;
                }
                *(float2*)&C[i0] = v0;
                *(float2*)&C[i1] = v1;
            } else if (c < N) {
                float b0 = (bias1 ? bias1[c] : 0.f) + (bias2 ? bias2[c] : 0.f);
                long long i0 = (long long)r * ldc + c;
                long long i1 = (long long)(r + 8) * ldc + c;
                float v0 = acc[mt][nt][0] + b0, v1 = acc[mt][nt][2] + b0;
                if (accFlag) { v0 += C[i0]; v1 += C[i1]; }
                C[i0] = v0;
                C[i1] = v1;
            }
        }
    }
#undef GLOAD
#undef SSTORE
}

// ---- K1: xin = concat(c_t_1, emb[y]) ----
__global__ void k_build_xin(const int* __restrict__ y, const float* __restrict__ ct1,
                            const float* __restrict__ emb, float* __restrict__ xin) {
    int b = blockIdx.x;
    int yy = y[b];
    for (int i = threadIdx.x; i < 1152; i += blockDim.x)
        xin[b * 1152 + i] = (i < 1024) ? ct1[b * 1024 + i] : emb[yy * 128 + (i - 1024)];
}

// ---- LSTM cell elementwise ----
__global__ void k_lstm(const float* __restrict__ gates, const float* __restrict__ c0,
                       float* __restrict__ out, float* __restrict__ sthat,
                       float* __restrict__ hct) {
    int b = blockIdx.x, j = threadIdx.x;   // 512 threads
    const float* g = gates + b * 2048;
    float ig = g[j], fg = g[512 + j], gg = g[1024 + j], og = g[1536 + j];
    float c = sigmoidf_(fg) * c0[b * 512 + j] + sigmoidf_(ig) * tanhf(gg);
    float h = sigmoidf_(og) * tanhf(c);
    out[O_H + b * 512 + j] = h;
    out[O_C + b * 512 + j] = c;
    sthat[b * 1024 + j] = h;
    sthat[b * 1024 + 512 + j] = c;
    hct[b * 1536 + j] = h;
}

// ---- attention scores: warp-per-t, no block syncs in the hot loop ----
__global__ __launch_bounds__(256) void k_attn_scores(const float* __restrict__ encf,
                                                     const float* __restrict__ decfea,
                                                     const float* __restrict__ cov,
                                                     const float* __restrict__ Wc,
                                                     const float* __restrict__ vw,
                                                     float* __restrict__ scores) {
    __shared__ float4 df[256], wc[256], vv[256];
    int b = blockIdx.x, tid = threadIdx.x;
    df[tid] = ((const float4*)(decfea + b * 1024))[tid];
    wc[tid] = ((const float4*)Wc)[tid];
    vv[tid] = ((const float4*)vw)[tid];
    __syncthreads();
    int w = tid >> 5, lane = tid & 31;
#pragma unroll
    for (int i = 0; i < 2; i++) {
        int tt = blockIdx.y * 16 + w * 2 + i;
        float cv = cov[b * 400 + tt];
        const float4* ef = (const float4*)(encf + ((long long)b * 400 + tt) * 1024);
        float local = 0.f;
#pragma unroll
        for (int j = 0; j < 8; j++) {
            int idx = lane + j * 32;
            float4 e4 = ef[idx];
            float4 d4 = df[idx], w4 = wc[idx], v4 = vv[idx];
            local += tanhf(e4.x + d4.x + cv * w4.x) * v4.x;
            local += tanhf(e4.y + d4.y + cv * w4.y) * v4.y;
            local += tanhf(e4.z + d4.z + cv * w4.z) * v4.z;
            local += tanhf(e4.w + d4.w + cv * w4.w) * v4.w;
        }
        local = warpReduceSum(local);
        if (lane == 0) scores[b * 400 + tt] = local;
    }
}

// ---- softmax over T, masking, renorm, coverage update ----
__global__ __launch_bounds__(128) void k_attn_softmax(const float* __restrict__ scores,
                                                      const float* __restrict__ mask,
                                                      const float* __restrict__ cov,
                                                      float* __restrict__ out) {
    __shared__ float sc[400];
    __shared__ float red[4];
    int b = blockIdx.x, tid = threadIdx.x;
    float mx = -1e30f;
    for (int t = tid; t < 400; t += 128) {
        float v = scores[b * 400 + t];
        sc[t] = v;
        mx = fmaxf(mx, v);
    }
    mx = warpReduceMax(mx);
    if ((tid & 31) == 0) red[tid >> 5] = mx;
    __syncthreads();
    mx = fmaxf(fmaxf(red[0], red[1]), fmaxf(red[2], red[3]));
    __syncthreads();

    float s = 0.f;
    for (int t = tid; t < 400; t += 128) {
        float e = expf(sc[t] - mx);
        sc[t] = e;
        s += e;
    }
    s = warpReduceSum(s);
    if ((tid & 31) == 0) red[tid >> 5] = s;
    __syncthreads();
    float denom = red[0] + red[1] + red[2] + red[3];
    __syncthreads();

    float s2 = 0.f;
    for (int t = tid; t < 400; t += 128) {
        float m = sc[t] / denom * mask[b * 400 + t];
        sc[t] = m;
        s2 += m;
    }
    s2 = warpReduceSum(s2);
    if ((tid & 31) == 0) red[tid >> 5] = s2;
    __syncthreads();
    float denom2 = red[0] + red[1] + red[2] + red[3] + EPSf;

    for (int t = tid; t < 400; t += 128) {
        float a = sc[t] / denom2;
        out[O_ATTN + b * 400 + t] = a;
        out[O_COV + b * 400 + t] = cov[b * 400 + t] + a;
    }
}

// ---- context vector ----
__global__ __launch_bounds__(256) void k_context(const float* __restrict__ encout,
                                                 const float* __restrict__ outbuf,
                                                 float* __restrict__ out,
                                                 float* __restrict__ hct) {
    __shared__ float at[400];
    int b = blockIdx.x;
    for (int i = threadIdx.x; i < 400; i += 256) at[i] = outbuf[O_ATTN + b * 400 + i];
    __syncthreads();
    int n = blockIdx.y * 256 + threadIdx.x;
    const float* ep = encout + (long long)b * 400 * 1024 + n;
    float a0 = 0.f, a1 = 0.f, a2 = 0.f, a3 = 0.f;
    for (int t = 0; t < 400; t += 4) {
        a0 += at[t + 0] * ep[(t + 0) * 1024];
        a1 += at[t + 1] * ep[(t + 1) * 1024];
        a2 += at[t + 2] * ep[(t + 2) * 1024];
        a3 += at[t + 3] * ep[(t + 3) * 1024];
    }
    float acc = (a0 + a1) + (a2 + a3);
    out[O_CT + b * 1024 + n] = acc;
    hct[b * 1536 + 512 + n] = acc;
}

// ---- pointer-generator gate ----
__global__ __launch_bounds__(256) void k_pgen(const float* __restrict__ outbuf,
                                              const float* __restrict__ sthat,
                                              const float* __restrict__ x,
                                              const float* __restrict__ Wpg,
                                              const float* __restrict__ bpg,
                                              float* __restrict__ out) {
    __shared__ float red[8];
    int b = blockIdx.x, tid = threadIdx.x;
    float local = 0.f;
    for (int i = tid; i < 2176; i += 256) {
        float v;
        if (i < 1024)       v = outbuf[O_CT + b * 1024 + i];
        else if (i < 2048)  v = sthat[b * 1024 + (i - 1024)];
        else                v = x[b * 128 + (i - 2048)];
        local += Wpg[i] * v;
    }
    local = warpReduceSum(local);
    if ((tid & 31) == 0) red[tid >> 5] = local;
    __syncthreads();
    if (tid == 0) {
        float s = 0.f;
#pragma unroll
        for (int w = 0; w < 8; w++) s += red[w];
        out[O_PGEN + b] = sigmoidf_(s + bpg[0]);
    }
}

// ---- vocab softmax: online max+sum (single read pass) + scale pass ----
__global__ __launch_bounds__(256) void k_vocab_softmax(float* __restrict__ out) {
    __shared__ float rm[8], rs[8];
    int b = blockIdx.x, tid = threadIdx.x;
    float* row = out + (long long)b * Vn;

    float m = -1e30f, s = 0.f;
    for (int i = tid; i < Vn; i += 256) {
        float v = row[i];
        if (v > m) { s *= expf(m - v); m = v; }
        s += expf(v - m);
    }
#pragma unroll
    for (int o = 16; o > 0; o >>= 1) {
        float m2 = __shfl_xor_sync(0xffffffffu, m, o);
        float s2 = __shfl_xor_sync(0xffffffffu, s, o);
        float M = fmaxf(m, m2);
        s = s * expf(m - M) + s2 * expf(m2 - M);
        m = M;
    }
    if ((tid & 31) == 0) { rm[tid >> 5] = m; rs[tid >> 5] = s; }
    __syncthreads();
    float M = rm[0];
#pragma unroll
    for (int w = 1; w < 8; w++) M = fmaxf(M, rm[w]);
    float S = 0.f;
#pragma unroll
    for (int w = 0; w < 8; w++) S += rs[w] * expf(rm[w] - M);

    float scale = out[O_PGEN + b] / S;
    for (int i = tid; i < Vn; i += 256) row[i] = expf(row[i] - M) * scale;
}

// ---- pointer scatter-add ----
__global__ void k_scatter(const int* __restrict__ ebev, const float* __restrict__ outbuf,
                          float* __restrict__ out) {
    int idx = blockIdx.x * blockDim.x + threadIdx.x;
    if (idx >= Bn * Tn) return;
    int b = idx / Tn;
    float add = (1.f - outbuf[O_PGEN + b]) * outbuf[O_ATTN + idx];
    atomicAdd(&out[(long long)b * Vn + ebev[idx]], add);
}

extern "C" void kernel_launch(void* const* d_in, const int* in_sizes, int n_in,
                              void* d_out, int out_size) {
    const int*   y      = (const int*)d_in[0];
    const float* h0     = (const float*)d_in[1];
    const float* c0     = (const float*)d_in[2];
    const float* ct1    = (const float*)d_in[3];
    const float* encout = (const float*)d_in[4];
    const float* encf   = (const float*)d_in[5];
    const float* mask   = (const float*)d_in[6];
    const int*   ebev   = (const int*)d_in[7];
    const float* cov    = (const float*)d_in[8];
    const float* emb    = (const float*)d_in[9];
    const float* Wc     = (const float*)d_in[10];
    const float* Wdp    = (const float*)d_in[11];
    const float* bdp    = (const float*)d_in[12];
    const float* vw     = (const float*)d_in[13];
    const float* Wxc    = (const float*)d_in[14];
    const float* bxc    = (const float*)d_in[15];
    const float* Wih    = (const float*)d_in[16];
    const float* Whh    = (const float*)d_in[17];
    const float* bih    = (const float*)d_in[18];
    const float* bhh    = (const float*)d_in[19];
    const float* Wpg    = (const float*)d_in[20];
    const float* bpg    = (const float*)d_in[21];
    const float* Wo1    = (const float*)d_in[22];
    const float* bo1    = (const float*)d_in[23];
    const float* Wo2    = (const float*)d_in[24];
    const float* bo2    = (const float*)d_in[25];
    float* out = (float*)d_out;

    float* scr = nullptr;
    cudaGetSymbolAddress((void**)&scr, g_scratch);
    float* xin    = scr + OFF_XIN;
    float* x      = scr + OFF_X;
    float* gates  = scr + OFF_GATES;
    float* sthat  = scr + OFF_STHAT;
    float* decfea = scr + OFF_DECFEA;
    float* scores = scr + OFF_SCORES;
    float* hct    = scr + OFF_HCT;
    float* out1   = scr + OFF_OUT1;

    const int SMEM_BIG   = (2 * 128 * 36 + 2 * 128 * 36) * 4;  // 73728
    const int SMEM_SMALL = (2 * 128 * 36 + 2 * 64 * 36) * 4;   // 55296
    cudaFuncSetAttribute(k_mma<4>, cudaFuncAttributeMaxDynamicSharedMemorySize, SMEM_BIG);
    cudaFuncSetAttribute(k_mma<2>, cudaFuncAttributeMaxDynamicSharedMemorySize, SMEM_SMALL);

    // x = concat(c_t_1, emb[y]) @ W_xc^T + b_xc
    k_build_xin<<<128, 256>>>(y, ct1, emb, xin);
    k_mma<2><<<2, 128, SMEM_SMALL>>>(xin, Wxc, bxc, nullptr, x, 128, 1152, 1152, 128, 0);

    // gates = x @ W_ih^T + (b_ih + b_hh) + h0 @ W_hh^T
    k_mma<2><<<32, 128, SMEM_SMALL>>>(x,  Wih, bih, bhh, gates, 2048, 128, 128, 2048, 0);
    k_mma<2><<<32, 128, SMEM_SMALL>>>(h0, Whh, nullptr, nullptr, gates, 2048, 512, 512, 2048, 1);
    k_lstm<<<128, 512>>>(gates, c0, out, sthat, hct);

    // attention
    k_mma<2><<<16, 128, SMEM_SMALL>>>(sthat, Wdp, bdp, nullptr, decfea, 1024, 1024, 1024, 1024, 0);
    k_attn_scores<<<dim3(128, 25), 256>>>(encf, decfea, cov, Wc, vw, scores);
    k_attn_softmax<<<128, 128>>>(scores, mask, cov, out);
    k_context<<<dim3(128, 4), 256>>>(encout, out, out, hct);

    // p_gen
    k_pgen<<<128, 256>>>(out, sthat, x, Wpg, bpg, out);

    // vocab distribution (logits straight into final_dist region)
    k_mma<2><<<8, 128, SMEM_SMALL>>>(hct, Wo1, bo1, nullptr, out1, 512, 1536, 1536, 512, 0);
    k_mma<4><<<391, 256, SMEM_BIG>>>(out1, Wo2, bo2, nullptr, out, 50000, 512, 512, 50000, 0);
    k_vocab_softmax<<<128, 256>>>(out);

    // pointer mixing
    k_scatter<<<200, 256>>>(ebev, out, out);
}

// round 9
// speedup vs baseline: 1.9106x; 1.0038x over previous
#include <cuda_runtime.h>
#include <math.h>
#include <stdint.h>

#define Bn   128
#define Tn   400
#define Vn   50000
#define EPSf 1e-12f

// ---- output layout (floats): concat of reference returns ----
#define O_FINAL 0
#define O_H     6400000
#define O_C     6465536
#define O_CT    6531072
#define O_ATTN  6662144
#define O_PGEN  6713344
#define O_COV   6713472

// ---- scratch ----
#define OFF_XIN    0        // [128,1152]
#define OFF_X      147456   // [128,128]
#define OFF_GATES  163840   // [128,2048]
#define OFF_STHAT  425984   // [128,1024]
#define OFF_DECFEA 557056   // [128,1024]
#define OFF_SCORES 688128   // [128,400]
#define OFF_HCT    739328   // [128,1536]
#define OFF_OUT1   935936   // [128,512]
#define SCRATCH_FLOATS 1001472

__device__ float g_scratch[SCRATCH_FLOATS];

__device__ __forceinline__ float warpReduceSum(float v) {
#pragma unroll
    for (int o = 16; o > 0; o >>= 1) v += __shfl_xor_sync(0xffffffffu, v, o);
    return v;
}
__device__ __forceinline__ float warpReduceMax(float v) {
#pragma unroll
    for (int o = 16; o > 0; o >>= 1) v = fmaxf(v, __shfl_xor_sync(0xffffffffu, v, o));
    return v;
}
__device__ __forceinline__ float sigmoidf_(float x) { return 1.f / (1.f + expf(-x)); }

__device__ __forceinline__ uint32_t f2tf32(float f) {
    uint32_t u;
    asm("cvt.rna.tf32.f32 %0, %1;" : "=r"(u) : "f"(f));
    return u;
}

__device__ __forceinline__ void mma_tf32(float* c, const uint32_t* a, const uint32_t* b) {
    asm("mma.sync.aligned.m16n8k8.row.col.f32.tf32.tf32.f32 "
        "{%0,%1,%2,%3}, {%4,%5,%6,%7}, {%8,%9}, {%0,%1,%2,%3};"
        : "+f"(c[0]), "+f"(c[1]), "+f"(c[2]), "+f"(c[3])
        : "r"(a[0]), "r"(a[1]), "r"(a[2]), "r"(a[3]), "r"(b[0]), "r"(b[1]));
}

// ================= tf32 tensor-core GEMM =================
// C[128, N] = A[128, K](lda) @ B[N, K]^T + bias1 + bias2 (+ C if acc)
// M = 128 always (1 block in M). grid.x = N tiles of (WN*32).
// 2 warps along M (64 rows each), WN warps along N (32 cols each).
// K must be a multiple of 32.
template<int WN>
__global__ void __launch_bounds__(WN * 64) k_mma(
        const float* __restrict__ A, const float* __restrict__ B,
        const float* __restrict__ bias1, const float* __restrict__ bias2,
        float* __restrict__ C, int N, int K, int lda, int ldc, int accFlag) {
    constexpr int NTHR = WN * 64;
    constexpr int TN   = WN * 32;
    constexpr int AF4  = 1024 / NTHR;       // A float4s per thread per chunk
    constexpr int BF4  = (TN * 8) / NTHR;   // B float4s per thread per chunk

    extern __shared__ uint32_t sm[];
    uint32_t* As = sm;                      // [2][128][36]
    uint32_t* Bs = sm + 2 * 128 * 36;       // [2][TN][36]

    const int tid  = threadIdx.x;
    const int wid  = tid >> 5, lane = tid & 31;
    const int g    = lane >> 2, t = lane & 3;
    const int n0   = blockIdx.x * TN;
    const int mw   = (wid / WN) * 64;
    const int nw   = (wid % WN) * 32;

    float acc[4][4][4] = {};
    float4 apf[AF4], bpf[BF4];

    const int nchunks = K >> 5;

#define GLOAD(KC)                                                              \
    {                                                                          \
        const float* Ap = A + (KC) * 32;                                       \
        _Pragma("unroll")                                                      \
        for (int i = 0; i < AF4; i++) {                                        \
            int e = tid + i * NTHR;                                            \
            int r = e >> 3, c4 = (e & 7) * 4;                                  \
            apf[i] = *(const float4*)(Ap + (long long)r * lda + c4);           \
        }                                                                      \
        const float* Bp = B + (KC) * 32;                                       \
        _Pragma("unroll")                                                      \
        for (int i = 0; i < BF4; i++) {                                        \
            int e = tid + i * NTHR;                                            \
            int r = e >> 3, c4 = (e & 7) * 4;                                  \
            int rg = n0 + r;                                                   \
            bpf[i] = (rg < N) ? *(const float4*)(Bp + (long long)rg * K + c4)  \
                              : make_float4(0.f, 0.f, 0.f, 0.f);               \
        }                                                                      \
    }

#define SSTORE(BUF)                                                            \
    {                                                                          \
        uint32_t* Asb = As + (BUF) * (128 * 36);                               \
        _Pragma("unroll")                                                      \
        for (int i = 0; i < AF4; i++) {                                        \
            int e = tid + i * NTHR;                                            \
            int r = e >> 3, c4 = (e & 7) * 4;                                  \
            uint4 u = make_uint4(f2tf32(apf[i].x), f2tf32(apf[i].y),           \
                                 f2tf32(apf[i].z), f2tf32(apf[i].w));          \
            *(uint4*)(Asb + r * 36 + c4) = u;                                  \
        }                                                                      \
        uint32_t* Bsb = Bs + (BUF) * (TN * 36);                                \
        _Pragma("unroll")                                                      \
        for (int i = 0; i < BF4; i++) {                                        \
            int e = tid + i * NTHR;                                            \
            int r = e >> 3, c4 = (e & 7) * 4;                                  \
            uint4 u = make_uint4(f2tf32(bpf[i].x), f2tf32(bpf[i].y),           \
                                 f2tf32(bpf[i].z), f2tf32(bpf[i].w));          \
            *(uint4*)(Bsb + r * 36 + c4) = u;                                  \
        }                                                                      \
    }

    GLOAD(0);
    SSTORE(0);
    __syncthreads();

    int buf = 0;
    for (int kc = 0; kc < nchunks; kc++) {
        bool more = (kc + 1 < nchunks);
        if (more) GLOAD(kc + 1);

        const uint32_t* Asb = As + buf * (128 * 36);
        const uint32_t* Bsb = Bs + buf * (TN * 36);
#pragma unroll
        for (int kk = 0; kk < 32; kk += 8) {
            uint32_t af[4][4], bf[4][2];
#pragma unroll
            for (int mt = 0; mt < 4; mt++) {
                const uint32_t* p = Asb + (mw + mt * 16 + g) * 36 + kk + t;
                af[mt][0] = p[0];
                af[mt][2] = p[4];
                af[mt][1] = p[8 * 36];
                af[mt][3] = p[8 * 36 + 4];
            }
#pragma unroll
            for (int nt = 0; nt < 4; nt++) {
                const uint32_t* p = Bsb + (nw + nt * 8 + g) * 36 + kk + t;
                bf[nt][0] = p[0];
                bf[nt][1] = p[4];
            }
#pragma unroll
            for (int mt = 0; mt < 4; mt++)
#pragma unroll
                for (int nt = 0; nt < 4; nt++)
                    mma_tf32(acc[mt][nt], af[mt], bf[nt]);
        }

        if (more) {
            SSTORE(buf ^ 1);
            __syncthreads();
        }
        buf ^= 1;
    }

    // epilogue
#pragma unroll
    for (int mt = 0; mt < 4; mt++) {
        int r = mw + mt * 16 + g;
#pragma unroll
        for (int nt = 0; nt < 4; nt++) {
            int c = n0 + nw + nt * 8 + 2 * t;
            if (c + 1 < N) {
                float b0 = (bias1 ? bias1[c] : 0.f) + (bias2 ? bias2[c] : 0.f);
                float b1 = (bias1 ? bias1[c + 1] : 0.f) + (bias2 ? bias2[c + 1] : 0.f);
                long long i0 = (long long)r * ldc + c;
                long long i1 = (long long)(r + 8) * ldc + c;
                float2 v0 = make_float2(acc[mt][nt][0] + b0, acc[mt][nt][1] + b1);
                float2 v1 = make_float2(acc[mt][nt][2] + b0, acc[mt][nt][3] + b1);
                if (accFlag) {
                    float2 o0 = *(float2*)&C[i0], o1 = *(float2*)&C[i1];
                    v0.x += o0.x; v0.y += o0.y; v1.x += o1.x; v1.y += o1.y;
                }
                *(float2*)&C[i0] = v0;
                *(float2*)&C[i1] = v1;
            } else if (c < N) {
                float b0 = (bias1 ? bias1[c] : 0.f) + (bias2 ? bias2[c] : 0.f);
                long long i0 = (long long)r * ldc + c;
                long long i1 = (long long)(r + 8) * ldc + c;
                float v0 = acc[mt][nt][0] + b0, v1 = acc[mt][nt][2] + b0;
                if (accFlag) { v0 += C[i0]; v1 += C[i1]; }
                C[i0] = v0;
                C[i1] = v1;
            }
        }
    }
#undef GLOAD
#undef SSTORE
}

// ---- K1: xin = concat(c_t_1, emb[y]) ----
__global__ void k_build_xin(const int* __restrict__ y, const float* __restrict__ ct1,
                            const float* __restrict__ emb, float* __restrict__ xin) {
    int b = blockIdx.x;
    int yy = y[b];
    for (int i = threadIdx.x; i < 1152; i += blockDim.x)
        xin[b * 1152 + i] = (i < 1024) ? ct1[b * 1024 + i] : emb[yy * 128 + (i - 1024)];
}

// ---- LSTM cell elementwise ----
__global__ void k_lstm(const float* __restrict__ gates, const float* __restrict__ c0,
                       float* __restrict__ out, float* __restrict__ sthat,
                       float* __restrict__ hct) {
    int b = blockIdx.x, j = threadIdx.x;   // 512 threads
    const float* g = gates + b * 2048;
    float ig = g[j], fg = g[512 + j], gg = g[1024 + j], og = g[1536 + j];
    float c = sigmoidf_(fg) * c0[b * 512 + j] + sigmoidf_(ig) * tanhf(gg);
    float h = sigmoidf_(og) * tanhf(c);
    out[O_H + b * 512 + j] = h;
    out[O_C + b * 512 + j] = c;
    sthat[b * 1024 + j] = h;
    sthat[b * 1024 + 512 + j] = c;
    hct[b * 1536 + j] = h;
}

// ---- attention scores: warp-per-t, no block syncs in the hot loop ----
__global__ __launch_bounds__(256) void k_attn_scores(const float* __restrict__ encf,
                                                     const float* __restrict__ decfea,
                                                     const float* __restrict__ cov,
                                                     const float* __restrict__ Wc,
                                                     const float* __restrict__ vw,
                                                     float* __restrict__ scores) {
    __shared__ float4 df[256], wc[256], vv[256];
    int b = blockIdx.x, tid = threadIdx.x;
    df[tid] = ((const float4*)(decfea + b * 1024))[tid];
    wc[tid] = ((const float4*)Wc)[tid];
    vv[tid] = ((const float4*)vw)[tid];
    __syncthreads();
    int w = tid >> 5, lane = tid & 31;
#pragma unroll
    for (int i = 0; i < 2; i++) {
        int tt = blockIdx.y * 16 + w * 2 + i;
        float cv = cov[b * 400 + tt];
        const float4* ef = (const float4*)(encf + ((long long)b * 400 + tt) * 1024);
        float local = 0.f;
#pragma unroll
        for (int j = 0; j < 8; j++) {
            int idx = lane + j * 32;
            float4 e4 = ef[idx];
            float4 d4 = df[idx], w4 = wc[idx], v4 = vv[idx];
            local += tanhf(e4.x + d4.x + cv * w4.x) * v4.x;
            local += tanhf(e4.y + d4.y + cv * w4.y) * v4.y;
            local += tanhf(e4.z + d4.z + cv * w4.z) * v4.z;
            local += tanhf(e4.w + d4.w + cv * w4.w) * v4.w;
        }
        local = warpReduceSum(local);
        if (lane == 0) scores[b * 400 + tt] = local;
    }
}

// ---- softmax over T, masking, renorm, coverage update ----
__global__ __launch_bounds__(128) void k_attn_softmax(const float* __restrict__ scores,
                                                      const float* __restrict__ mask,
                                                      const float* __restrict__ cov,
                                                      float* __restrict__ out) {
    __shared__ float sc[400];
    __shared__ float red[4];
    int b = blockIdx.x, tid = threadIdx.x;
    float mx = -1e30f;
    for (int t = tid; t < 400; t += 128) {
        float v = scores[b * 400 + t];
        sc[t] = v;
        mx = fmaxf(mx, v);
    }
    mx = warpReduceMax(mx);
    if ((tid & 31) == 0) red[tid >> 5] = mx;
    __syncthreads();
    mx = fmaxf(fmaxf(red[0], red[1]), fmaxf(red[2], red[3]));
    __syncthreads();

    float s = 0.f;
    for (int t = tid; t < 400; t += 128) {
        float e = expf(sc[t] - mx);
        sc[t] = e;
        s += e;
    }
    s = warpReduceSum(s);
    if ((tid & 31) == 0) red[tid >> 5] = s;
    __syncthreads();
    float denom = red[0] + red[1] + red[2] + red[3];
    __syncthreads();

    float s2 = 0.f;
    for (int t = tid; t < 400; t += 128) {
        float m = sc[t] / denom * mask[b * 400 + t];
        sc[t] = m;
        s2 += m;
    }
    s2 = warpReduceSum(s2);
    if ((tid & 31) == 0) red[tid >> 5] = s2;
    __syncthreads();
    float denom2 = red[0] + red[1] + red[2] + red[3] + EPSf;

    for (int t = tid; t < 400; t += 128) {
        float a = sc[t] / denom2;
        out[O_ATTN + b * 400 + t] = a;
        out[O_COV + b * 400 + t] = cov[b * 400 + t] + a;
    }
}

// ---- context vector ----
__global__ __launch_bounds__(256) void k_context(const float* __restrict__ encout,
                                                 const float* __restrict__ outbuf,
                                                 float* __restrict__ out,
                                                 float* __restrict__ hct) {
    __shared__ float at[400];
    int b = blockIdx.x;
    for (int i = threadIdx.x; i < 400; i += 256) at[i] = outbuf[O_ATTN + b * 400 + i];
    __syncthreads();
    int n = blockIdx.y * 256 + threadIdx.x;
    const float* ep = encout + (long long)b * 400 * 1024 + n;
    float a0 = 0.f, a1 = 0.f, a2 = 0.f, a3 = 0.f;
    for (int t = 0; t < 400; t += 4) {
        a0 += at[t + 0] * ep[(t + 0) * 1024];
        a1 += at[t + 1] * ep[(t + 1) * 1024];
        a2 += at[t + 2] * ep[(t + 2) * 1024];
        a3 += at[t + 3] * ep[(t + 3) * 1024];
    }
    float acc = (a0 + a1) + (a2 + a3);
    out[O_CT + b * 1024 + n] = acc;
    hct[b * 1536 + 512 + n] = acc;
}

// ---- pointer-generator gate ----
__global__ __launch_bounds__(256) void k_pgen(const float* __restrict__ outbuf,
                                              const float* __restrict__ sthat,
                                              const float* __restrict__ x,
                                              const float* __restrict__ Wpg,
                                              const float* __restrict__ bpg,
                                              float* __restrict__ out) {
    __shared__ float red[8];
    int b = blockIdx.x, tid = threadIdx.x;
    float local = 0.f;
    for (int i = tid; i < 2176; i += 256) {
        float v;
        if (i < 1024)       v = outbuf[O_CT + b * 1024 + i];
        else if (i < 2048)  v = sthat[b * 1024 + (i - 1024)];
        else                v = x[b * 128 + (i - 2048)];
        local += Wpg[i] * v;
    }
    local = warpReduceSum(local);
    if ((tid & 31) == 0) red[tid >> 5] = local;
    __syncthreads();
    if (tid == 0) {
        float s = 0.f;
#pragma unroll
        for (int w = 0; w < 8; w++) s += red[w];
        out[O_PGEN + b] = sigmoidf_(s + bpg[0]);
    }
}

// ---- vocab softmax: online max+sum (single read pass) + scale pass ----
__global__ __launch_bounds__(256) void k_vocab_softmax(float* __restrict__ out) {
    __shared__ float rm[8], rs[8];
    int b = blockIdx.x, tid = threadIdx.x;
    float* row = out + (long long)b * Vn;

    float m = -1e30f, s = 0.f;
    for (int i = tid; i < Vn; i += 256) {
        float v = row[i];
        if (v > m) { s *= expf(m - v); m = v; }
        s += expf(v - m);
    }
#pragma unroll
    for (int o = 16; o > 0; o >>= 1) {
        float m2 = __shfl_xor_sync(0xffffffffu, m, o);
        float s2 = __shfl_xor_sync(0xffffffffu, s, o);
        float M = fmaxf(m, m2);
        s = s * expf(m - M) + s2 * expf(m2 - M);
        m = M;
    }
    if ((tid & 31) == 0) { rm[tid >> 5] = m; rs[tid >> 5] = s; }
    __syncthreads();
    float M = rm[0];
#pragma unroll
    for (int w = 1; w < 8; w++) M = fmaxf(M, rm[w]);
    float S = 0.f;
#pragma unroll
    for (int w = 0; w < 8; w++) S += rs[w] * expf(rm[w] - M);

    float scale = out[O_PGEN + b] / S;
    for (int i = tid; i < Vn; i += 256) row[i] = expf(row[i] - M) * scale;
}

// ---- pointer scatter-add ----
__global__ void k_scatter(const int* __restrict__ ebev, const float* __restrict__ outbuf,
                          float* __restrict__ out) {
    int idx = blockIdx.x * blockDim.x + threadIdx.x;
    if (idx >= Bn * Tn) return;
    int b = idx / Tn;
    float add = (1.f - outbuf[O_PGEN + b]) * outbuf[O_ATTN + idx];
    atomicAdd(&out[(long long)b * Vn + ebev[idx]], add);
}

extern "C" void kernel_launch(void* const* d_in, const int* in_sizes, int n_in,
                              void* d_out, int out_size) {
    const int*   y      = (const int*)d_in[0];
    const float* h0     = (const float*)d_in[1];
    const float* c0     = (const float*)d_in[2];
    const float* ct1    = (const float*)d_in[3];
    const float* encout = (const float*)d_in[4];
    const float* encf   = (const float*)d_in[5];
    const float* mask   = (const float*)d_in[6];
    const int*   ebev   = (const int*)d_in[7];
    const float* cov    = (const float*)d_in[8];
    const float* emb    = (const float*)d_in[9];
    const float* Wc     = (const float*)d_in[10];
    const float* Wdp    = (const float*)d_in[11];
    const float* bdp    = (const float*)d_in[12];
    const float* vw     = (const float*)d_in[13];
    const float* Wxc    = (const float*)d_in[14];
    const float* bxc    = (const float*)d_in[15];
    const float* Wih    = (const float*)d_in[16];
    const float* Whh    = (const float*)d_in[17];
    const float* bih    = (const float*)d_in[18];
    const float* bhh    = (const float*)d_in[19];
    const float* Wpg    = (const float*)d_in[20];
    const float* bpg    = (const float*)d_in[21];
    const float* Wo1    = (const float*)d_in[22];
    const float* bo1    = (const float*)d_in[23];
    const float* Wo2    = (const float*)d_in[24];
    const float* bo2    = (const float*)d_in[25];
    float* out = (float*)d_out;

    float* scr = nullptr;
    cudaGetSymbolAddress((void**)&scr, g_scratch);
    float* xin    = scr + OFF_XIN;
    float* x      = scr + OFF_X;
    float* gates  = scr + OFF_GATES;
    float* sthat  = scr + OFF_STHAT;
    float* decfea = scr + OFF_DECFEA;
    float* scores = scr + OFF_SCORES;
    float* hct    = scr + OFF_HCT;
    float* out1   = scr + OFF_OUT1;

    const int SMEM_BIG   = (2 * 128 * 36 + 2 * 128 * 36) * 4;  // 73728
    const int SMEM_SMALL = (2 * 128 * 36 + 2 * 64 * 36) * 4;   // 55296
    cudaFuncSetAttribute(k_mma<4>, cudaFuncAttributeMaxDynamicSharedMemorySize, SMEM_BIG);
    cudaFuncSetAttribute(k_mma<2>, cudaFuncAttributeMaxDynamicSharedMemorySize, SMEM_SMALL);

    // x = concat(c_t_1, emb[y]) @ W_xc^T + b_xc
    k_build_xin<<<128, 256>>>(y, ct1, emb, xin);
    k_mma<2><<<2, 128, SMEM_SMALL>>>(xin, Wxc, bxc, nullptr, x, 128, 1152, 1152, 128, 0);

    // gates = x @ W_ih^T + (b_ih + b_hh) + h0 @ W_hh^T
    k_mma<2><<<32, 128, SMEM_SMALL>>>(x,  Wih, bih, bhh, gates, 2048, 128, 128, 2048, 0);
    k_mma<2><<<32, 128, SMEM_SMALL>>>(h0, Whh, nullptr, nullptr, gates, 2048, 512, 512, 2048, 1);
    k_lstm<<<128, 512>>>(gates, c0, out, sthat, hct);

    // attention
    k_mma<2><<<16, 128, SMEM_SMALL>>>(sthat, Wdp, bdp, nullptr, decfea, 1024, 1024, 1024, 1024, 0);
    k_attn_scores<<<dim3(128, 25), 256>>>(encf, decfea, cov, Wc, vw, scores);
    k_attn_softmax<<<128, 128>>>(scores, mask, cov, out);
    k_context<<<dim3(128, 4), 256>>>(encout, out, out, hct);

    // p_gen
    k_pgen<<<128, 256>>>(out, sthat, x, Wpg, bpg, out);

    // vocab distribution (logits straight into final_dist region)
    k_mma<2><<<8, 128, SMEM_SMALL>>>(hct, Wo1, bo1, nullptr, out1, 512, 1536, 1536, 512, 0);
    k_mma<4><<<391, 256, SMEM_BIG>>>(out1, Wo2, bo2, nullptr, out, 50000, 512, 512, 50000, 0);
    k_vocab_softmax<<<128, 256>>>(out);

    // pointer mixing
    k_scatter<<<200, 256>>>(ebev, out, out);
}